// round 13
// baseline (speedup 1.0000x reference)
#include <cuda_runtime.h>

// PManifold: B=64, H=2, N=512, K=64, M=16  — fused single kernel, R12.
// Collapse (see prior rounds): v_m = A0*[m==0]+A1*[m==1]+sum_k F_k*theta_k[m];
// log0(exp0(v)) == min(||v||, atanh(MX))/||v|| * v exactly.
// R12: 2 MUFU/eval (rsqrt + lg2, via atanh(r) = ln(1+r) - 0.5*ln(1-s)) with
// the deg-8 A&S 4.1.44 poly for ln(1+r)/r, and ALL non-MUFU eval arithmetic
// in packed f32x2 (FFMA2) over the lane's (k, k+32) pair — MUFU floor drops
// 5.3K->3.5K cyc/SMSP without the scalar-poly slot blowup that sank R10.

#define B_ 64
#define H_ 2
#define N_ 512
#define K_ 64
#define M_ 16

#define EPS2_ 1e-14f
#define ATMX_ 6.1023535f                       // atanh(fp32(1-1e-5))
#define HALF_LN2_ 0.34657359027997264f

// A&S 4.1.44: ln(1+x)/x = A1 + A2 x + ... + A8 x^7 (|eps_ln| <= 3e-8 on [0,1])
#define PA1_  0.9999964239f
#define PA2_ -0.4998741238f
#define PA3_  0.3317990258f
#define PA4_ -0.2407338084f
#define PA5_  0.1676540711f
#define PA6_ -0.0953293897f
#define PA7_  0.0360884937f
#define PA8_ -0.0064535442f

typedef unsigned long long u64;

__device__ __forceinline__ u64 pk2(float lo, float hi) {
    u64 r; asm("mov.b64 %0, {%1,%2};" : "=l"(r) : "f"(lo), "f"(hi)); return r;
}
__device__ __forceinline__ u64 pkb(float v) {          // broadcast pack
    u64 r; asm("mov.b64 %0, {%1,%1};" : "=l"(r) : "f"(v)); return r;
}
__device__ __forceinline__ void upk(float& lo, float& hi, u64 v) {
    asm("mov.b64 {%0,%1}, %2;" : "=f"(lo), "=f"(hi) : "l"(v));
}
__device__ __forceinline__ u64 fma2(u64 a, u64 b, u64 c) {
    u64 d; asm("fma.rn.f32x2 %0, %1, %2, %3;" : "=l"(d) : "l"(a), "l"(b), "l"(c)); return d;
}
__device__ __forceinline__ u64 add2(u64 a, u64 b) {
    u64 d; asm("add.rn.f32x2 %0, %1, %2;" : "=l"(d) : "l"(a), "l"(b)); return d;
}
__device__ __forceinline__ u64 mul2(u64 a, u64 b) {
    u64 d; asm("mul.rn.f32x2 %0, %1, %2;" : "=l"(d) : "l"(a), "l"(b)); return d;
}

__global__ __launch_bounds__(256, 4) void pm_fused(const float* __restrict__ in,
                                                   const float* __restrict__ theta,
                                                   float* __restrict__ out)
{
    __shared__ float4 e_pts[8][16];       // [r][k'-kbase]: (e0,e1,q,0)
    __shared__ float  th_t[M_][68];       // transposed theta: [m][k]
    __shared__ float4 tk_s[K_];           // per-k (2*t0, 2*t1, Dk+EPS2, 0)
    __shared__ float  F_sh[16][K_];       // [local output][k]

    const int bh    = blockIdx.x >> 2;          // b*2 + h
    const int kbase = (blockIdx.x & 3) << 4;    // 16 outputs per block
    const int h     = bh & 1;
    const int tid   = threadIdx.x;
    const int w     = tid >> 5;
    const int lane  = tid & 31;

    // ---- prologue: theta staging (transposed) + per-k constants ----
    {
        float4 tv = reinterpret_cast<const float4*>(theta + h * (K_ * M_))[tid];
        int k = tid >> 2, q = tid & 3;
        th_t[4 * q + 0][k] = tv.x;
        th_t[4 * q + 1][k] = tv.y;
        th_t[4 * q + 2][k] = tv.z;
        th_t[4 * q + 3][k] = tv.w;
        float p = fmaf(tv.x, tv.x, fmaf(tv.y, tv.y, fmaf(tv.z, tv.z, tv.w * tv.w)));
        p += __shfl_xor_sync(0xffffffffu, p, 1);
        p += __shfl_xor_sync(0xffffffffu, p, 2);
        if (q == 0) tk_s[k] = make_float4(tv.x + tv.x, tv.y + tv.y, p + EPS2_, 0.0f);
    }

    // ---- prologue: exp0 for this block's 128 points ----
    if (tid < 128) {
        int r = tid >> 4, j = tid & 15;
        float2 d = reinterpret_cast<const float2*>(in)[bh * N_ + r * 64 + kbase + j];
        float s   = fmaf(d.x, d.x, fmaf(d.y, d.y, EPS2_));
        float rin = rsqrtf(s);
        float n   = s * rin;
        float e2  = __expf(n + n);
        float big = (1.0f - __fdividef(2.0f, e2 + 1.0f)) * rin;
        float sml = fmaf(s, fmaf(s, 2.0f / 15.0f, -1.0f / 3.0f), 1.0f);
        float sc  = (s < 1e-3f) ? sml : big;
        e_pts[r][j] = make_float4(d.x * sc, d.y * sc, (sc * sc) * s, 0.0f);
    }
    __syncthreads();

    // ---- packed per-lane constants (a = k=lane, b = k=lane+32) ----
    const float4 ca = tk_s[lane];
    const float4 cb = tk_s[lane + 32];
    const u64 C0 = pk2(ca.x, cb.x);       // (2t0a, 2t0b)
    const u64 C1 = pk2(ca.y, cb.y);       // (2t1a, 2t1b)
    const u64 CD = pk2(ca.z, cb.z);       // (Da', Db')
    const u64 K8 = pkb(PA8_), K7 = pkb(PA7_), K6 = pkb(PA6_), K5 = pkb(PA5_);
    const u64 K4 = pkb(PA4_), K3 = pkb(PA3_), K2c = pkb(PA2_), K1 = pkb(PA1_);
    const u64 KH = pkb(-HALF_LN2_);

    // ---- main: warp w owns outputs kbase+2w+0/1, computed sequentially ----
    float A0s[2], A1s[2];
    #pragma unroll
    for (int oo = 0; oo < 2; ++oo) {
        const int col = 2 * w + oo;
        u64 F2 = 0, A02 = 0, A12 = 0;     // packed (a,b) accumulators
        #pragma unroll
        for (int r = 0; r < 8; ++r) {
            float4 e = e_pts[r][col];     // warp-broadcast LDS.128
            u64 ex2 = pkb(e.x), ey2 = pkb(e.y), ez2 = pkb(e.z);
            // s = q + 2t0 e0 + 2t1 e1 + (Dk+eps);  all terms >= 0, s < 0.956
            u64 s2 = fma2(C0, ex2, fma2(C1, ey2, add2(ez2, CD)));
            float sA, sB; upk(sA, sB, s2);
            float riA = rsqrtf(sA);       // MUFU
            float riB = rsqrtf(sB);
            float lA  = __log2f(1.0f - sA);   // MUFU
            float lB  = __log2f(1.0f - sB);
            u64 ri2 = pk2(riA, riB);
            u64 r2  = mul2(s2, ri2);          // r = ||x||
            u64 Lri = mul2(pk2(lA, lB), ri2); // lg2(1-s)/r
            // ln(1+r)/r, Horner deg-7 in r (packed)
            u64 p = fma2(K8, r2, K7);
            p = fma2(p, r2, K6);
            p = fma2(p, r2, K5);
            p = fma2(p, r2, K4);
            p = fma2(p, r2, K3);
            p = fma2(p, r2, K2c);
            p = fma2(p, r2, K1);
            // f = ln(1+r)/r - 0.5*ln2 * lg2(1-s)/r   (exact atanh split)
            u64 f2 = fma2(Lri, KH, p);
            F2  = add2(F2, f2);
            A02 = fma2(f2, ex2, A02);
            A12 = fma2(f2, ey2, A12);
        }
        float Fa, Fb, a0l, a0h, a1l, a1h;
        upk(Fa, Fb, F2);
        upk(a0l, a0h, A02);
        upk(a1l, a1h, A12);
        float A0 = a0l + a0h, A1 = a1l + a1h;
        #pragma unroll
        for (int o = 16; o; o >>= 1) {
            A0 += __shfl_xor_sync(0xffffffffu, A0, o);
            A1 += __shfl_xor_sync(0xffffffffu, A1, o);
        }
        F_sh[col][lane]      = Fa;
        F_sh[col][lane + 32] = Fb;
        A0s[oo] = A0;
        A1s[oo] = A1;
    }
    __syncwarp();

    // matvec: lane owns one (output o, component m); full 64-k dot product
    const int o = lane >> 4;
    const int m = lane & 15;
    const float4* t4p = reinterpret_cast<const float4*>(&th_t[m][0]);
    const float4* f4p = reinterpret_cast<const float4*>(&F_sh[2 * w + o][0]);
    float acc = 0.0f;
    #pragma unroll
    for (int j = 0; j < 16; ++j) {
        float4 t4 = t4p[j];
        float4 f4 = f4p[j];
        acc = fmaf(f4.x, t4.x, acc);
        acc = fmaf(f4.y, t4.y, acc);
        acc = fmaf(f4.z, t4.z, acc);
        acc = fmaf(f4.w, t4.w, acc);
    }

    float v = acc;                         // f fully scaled (no deferred ln2)
    if (m == 0) v += (o == 0) ? A0s[0] : A0s[1];
    if (m == 1) v += (o == 0) ? A1s[0] : A1s[1];

    // ||v||^2 over 16 components (xor stays within each 16-lane half)
    float ns2 = fmaf(v, v, EPS2_);
    #pragma unroll
    for (int off = 8; off; off >>= 1) ns2 += __shfl_xor_sync(0xffffffffu, ns2, off);
    float rin   = rsqrtf(ns2);
    float ns    = ns2 * rin;
    float scale = fminf(ns, ATMX_) * rin;  // log0(exp0(v)) scale, exact

    out[(bh * K_ + kbase + 2 * w) * M_ + lane] = scale * v;
}

extern "C" void kernel_launch(void* const* d_in, const int* in_sizes, int n_in,
                              void* d_out, int out_size)
{
    const float* inputs = (const float*)d_in[0];   // (B,H,N,2)
    const float* theta  = (const float*)d_in[1];   // (H,K,M)
    float* out = (float*)d_out;                    // (B,2,K,M)

    pm_fused<<<(B_ * H_ * K_) / 16, 256>>>(inputs, theta, out);
}